// round 2
// baseline (speedup 1.0000x reference)
#include <cuda_runtime.h>
#include <math.h>

#define Bdim 4
#define Tdim 2048
#define Cdim 1024
#define Hdim 16
#define Ddim 64
#define CSdim 16
#define NTdim (Tdim/CSdim)          // 128 chunks
#define BTdim (Bdim*Tdim)           // 8192
#define BHT   (Bdim*Hdim*Tdim)      // 131072
#define EPSLN 1e-5f

// Scratch (allocation-free rule: __device__ globals)
__device__ float g_qkv[3][(size_t)BHT*Ddim];   // q,k,v in [b,h,t,d]
__device__ float g_param[3][BHT];              // theta,alpha,eta in [b,h,t]
__device__ float g_o[(size_t)BTdim*Cdim];      // o (post final LN) in [b,t,c]

// ---------------------------------------------------------------------------
// K1: qkv = x @ W_attn + b_attn, scattered into [b,h,t,d] per q/k/v
// Classic SGEMM 128x128x8, 8x8 per thread, 256 threads.
// ---------------------------------------------------------------------------
__global__ __launch_bounds__(256) void gemm_qkv(const float* __restrict__ A,
                                                const float* __restrict__ Bw,
                                                const float* __restrict__ bias)
{
    const int K = Cdim, N = 3*Cdim;
    __shared__ float As[8][128];
    __shared__ float Bs[8][128];
    int tid = threadIdx.x;
    int row0 = blockIdx.y * 128, col0 = blockIdx.x * 128;
    int aRow = tid >> 1, aCol = (tid & 1) << 2;
    int bRow = tid >> 5, bCol = (tid & 31) << 2;
    int tr = tid >> 4, tc = tid & 15;

    float acc[8][8];
#pragma unroll
    for (int i = 0; i < 8; i++)
#pragma unroll
        for (int j = 0; j < 8; j++) acc[i][j] = 0.f;

    const float* Aptr = A  + (size_t)(row0 + aRow) * K + aCol;
    const float* Bptr = Bw + (size_t)bRow * N + col0 + bCol;

    for (int kt = 0; kt < K; kt += 8) {
        float4 av = *(const float4*)(Aptr + kt);
        As[aCol+0][aRow] = av.x; As[aCol+1][aRow] = av.y;
        As[aCol+2][aRow] = av.z; As[aCol+3][aRow] = av.w;
        float4 bv = *(const float4*)(Bptr + (size_t)kt * N);
        *(float4*)&Bs[bRow][bCol] = bv;
        __syncthreads();
#pragma unroll
        for (int kk = 0; kk < 8; kk++) {
            float a[8], bb[8];
#pragma unroll
            for (int i = 0; i < 8; i++) a[i]  = As[kk][tr*8 + i];
#pragma unroll
            for (int j = 0; j < 8; j++) bb[j] = Bs[kk][tc*8 + j];
#pragma unroll
            for (int i = 0; i < 8; i++)
#pragma unroll
                for (int j = 0; j < 8; j++) acc[i][j] += a[i] * bb[j];
        }
        __syncthreads();
    }
    // epilogue: scatter into head layout
#pragma unroll
    for (int i = 0; i < 8; i++) {
        int r = row0 + tr*8 + i;
        int b = r / Tdim, t = r % Tdim;
#pragma unroll
        for (int j = 0; j < 8; j++) {
            int col = col0 + tc*8 + j;
            int kind = col >> 10;          // /1024
            int cc = col & 1023;
            int h = cc >> 6, d = cc & 63;
            float v = acc[i][j] + bias[col];
            g_qkv[kind][(((size_t)b*Hdim + h)*Tdim + t)*Ddim + d] = v;
        }
    }
}

// ---------------------------------------------------------------------------
// K4: out = g_o @ W_proj + b_proj
// ---------------------------------------------------------------------------
__global__ __launch_bounds__(256) void gemm_proj(const float* __restrict__ Bw,
                                                 const float* __restrict__ bias,
                                                 float* __restrict__ out)
{
    const int K = Cdim, N = Cdim;
    const float* A = g_o;
    __shared__ float As[8][128];
    __shared__ float Bs[8][128];
    int tid = threadIdx.x;
    int row0 = blockIdx.y * 128, col0 = blockIdx.x * 128;
    int aRow = tid >> 1, aCol = (tid & 1) << 2;
    int bRow = tid >> 5, bCol = (tid & 31) << 2;
    int tr = tid >> 4, tc = tid & 15;

    float acc[8][8];
#pragma unroll
    for (int i = 0; i < 8; i++)
#pragma unroll
        for (int j = 0; j < 8; j++) acc[i][j] = 0.f;

    const float* Aptr = A  + (size_t)(row0 + aRow) * K + aCol;
    const float* Bptr = Bw + (size_t)bRow * N + col0 + bCol;

    for (int kt = 0; kt < K; kt += 8) {
        float4 av = *(const float4*)(Aptr + kt);
        As[aCol+0][aRow] = av.x; As[aCol+1][aRow] = av.y;
        As[aCol+2][aRow] = av.z; As[aCol+3][aRow] = av.w;
        float4 bv = *(const float4*)(Bptr + (size_t)kt * N);
        *(float4*)&Bs[bRow][bCol] = bv;
        __syncthreads();
#pragma unroll
        for (int kk = 0; kk < 8; kk++) {
            float a[8], bb[8];
#pragma unroll
            for (int i = 0; i < 8; i++) a[i]  = As[kk][tr*8 + i];
#pragma unroll
            for (int j = 0; j < 8; j++) bb[j] = Bs[kk][tc*8 + j];
#pragma unroll
            for (int i = 0; i < 8; i++)
#pragma unroll
                for (int j = 0; j < 8; j++) acc[i][j] += a[i] * bb[j];
        }
        __syncthreads();
    }
#pragma unroll
    for (int i = 0; i < 8; i++) {
        int r = row0 + tr*8 + i;
#pragma unroll
        for (int jj = 0; jj < 8; jj += 4) {
            int col = col0 + tc*8 + jj;
            float4 v;
            v.x = acc[i][jj+0] + bias[col+0];
            v.y = acc[i][jj+1] + bias[col+1];
            v.z = acc[i][jj+2] + bias[col+2];
            v.w = acc[i][jj+3] + bias[col+3];
            *(float4*)(out + (size_t)r * N + col) = v;
        }
    }
}

// ---------------------------------------------------------------------------
// K2: p = sigmoid(x @ W_param + b_param) -> theta/alpha/eta [b,h,t]
// block: 256 threads, 64 rows x 48 cols per block.
// ---------------------------------------------------------------------------
__global__ __launch_bounds__(256) void param_kernel(const float* __restrict__ x,
                                                    const float* __restrict__ W,
                                                    const float* __restrict__ bias)
{
    __shared__ float xs[64][68];
    __shared__ float Ws[64][48];
    int tid = threadIdx.x;
    int row0 = blockIdx.x * 64;
    int r = tid >> 2, q = tid & 3;

    float acc[12];
#pragma unroll
    for (int j = 0; j < 12; j++) acc[j] = 0.f;

    for (int kt = 0; kt < Cdim; kt += 64) {
        int lr = tid >> 2;
        int lc0 = (tid & 3) * 4;
#pragma unroll
        for (int tt = 0; tt < 4; tt++) {
            float4 v = *(const float4*)(x + (size_t)(row0 + lr) * Cdim + kt + lc0 + tt*16);
            xs[lr][lc0 + tt*16 + 0] = v.x;
            xs[lr][lc0 + tt*16 + 1] = v.y;
            xs[lr][lc0 + tt*16 + 2] = v.z;
            xs[lr][lc0 + tt*16 + 3] = v.w;
        }
#pragma unroll
        for (int tt = 0; tt < 12; tt++) {
            int idx = tid + tt * 256;
            int wr = idx / 48, wc = idx % 48;
            Ws[wr][wc] = W[(size_t)(kt + wr) * 48 + wc];
        }
        __syncthreads();
#pragma unroll
        for (int kk = 0; kk < 64; kk++) {
            float xv = xs[r][kk];
#pragma unroll
            for (int j = 0; j < 12; j++) acc[j] += xv * Ws[kk][q + 4*j];
        }
        __syncthreads();
    }
    int grow = row0 + r;
    int b = grow / Tdim, t = grow % Tdim;
#pragma unroll
    for (int j = 0; j < 12; j++) {
        int col = q + 4*j;
        int h = col / 3, ii = col % 3;
        float v = acc[j] + bias[col];
        v = 1.f / (1.f + expf(-v));
        g_param[ii][((size_t)b*Hdim + h)*Tdim + t] = v;
    }
}

// ---------------------------------------------------------------------------
// K3: chunked Titans scan. One block per (b,h). 512 threads.
// Thread (e = tid>>3, g = tid&7) owns S[8g..8g+8)[e], m likewise, in registers.
// ---------------------------------------------------------------------------
__global__ __launch_bounds__(512) void scan_kernel(const float* __restrict__ w,
                                                   const float* __restrict__ bln)
{
    __shared__ float k_s[16][64], q_s[16][64], v_s[16][64];
    __shared__ float kh_s[16][64], dkh_s[16][64], o_s[16][64];
    __shared__ float th_s[16], al_s[16], et_s[16];
    __shared__ float w_s[64], b_s[64];

    int tid  = threadIdx.x;
    int e    = tid >> 3, g = tid & 7;
    int lane = tid & 31, wid = tid >> 5;   // 16 warps, warp per chunk-row
    int bh = blockIdx.x;
    int b  = bh >> 4, h = bh & 15;

    const float* qg = g_qkv[0] + (size_t)bh * Tdim * Ddim;
    const float* kg = g_qkv[1] + (size_t)bh * Tdim * Ddim;
    const float* vg = g_qkv[2] + (size_t)bh * Tdim * Ddim;
    const float* thg = g_param[0] + (size_t)bh * Tdim;
    const float* alg = g_param[1] + (size_t)bh * Tdim;
    const float* etg = g_param[2] + (size_t)bh * Tdim;

    if (tid < 64) { w_s[tid] = w[h*64 + tid]; b_s[tid] = bln[h*64 + tid]; }

    float S[8], m[8];
#pragma unroll
    for (int i = 0; i < 8; i++) { S[i] = 0.f; m[i] = 0.f; }

    for (int ci = 0; ci < NTdim; ci++) {
        int base = ci * CSdim * Ddim;
        for (int idx = tid; idx < CSdim*Ddim; idx += 512) {
            ((float*)k_s)[idx] = kg[base + idx];
            ((float*)q_s)[idx] = qg[base + idx];
            ((float*)v_s)[idx] = vg[base + idx];
        }
        if (tid < 16) {
            th_s[tid] = thg[ci*16 + tid];
            al_s[tid] = alg[ci*16 + tid];
            et_s[tid] = etg[ci*16 + tid];
        }
        __syncthreads();

        // l2-normalize q,k rows (warp per row)
        {
            int c = wid;
            float k0 = k_s[c][lane], k1 = k_s[c][lane+32];
            float q0 = q_s[c][lane], q1 = q_s[c][lane+32];
            float sk = k0*k0 + k1*k1, sq = q0*q0 + q1*q1;
#pragma unroll
            for (int off = 16; off; off >>= 1) {
                sk += __shfl_xor_sync(0xffffffffu, sk, off);
                sq += __shfl_xor_sync(0xffffffffu, sq, off);
            }
            float rk = 1.f / fmaxf(sqrtf(sk), 1e-12f);
            float rq = 1.f / fmaxf(sqrtf(sq), 1e-12f);
            k_s[c][lane] = k0*rk; k_s[c][lane+32] = k1*rk;
            q_s[c][lane] = q0*rq; q_s[c][lane+32] = q1*rq;
        }
        __syncthreads();

        // kh = k @ S  (register partials + width-8 reduce)
#pragma unroll
        for (int c = 0; c < 16; c++) {
            float p = 0.f;
#pragma unroll
            for (int i = 0; i < 8; i++) p += k_s[c][8*g + i] * S[i];
            p += __shfl_xor_sync(0xffffffffu, p, 1);
            p += __shfl_xor_sync(0xffffffffu, p, 2);
            p += __shfl_xor_sync(0xffffffffu, p, 4);
            if (g == 0) kh_s[c][e] = p;
        }
        __syncthreads();

        // LN fwd + bwd per row: dkh = ln_bwd(kh, w, 2*(ln(kh)-v))
        {
            int c = wid;
            float x0 = kh_s[c][lane], x1 = kh_s[c][lane+32];
            float s = x0 + x1;
#pragma unroll
            for (int off = 16; off; off >>= 1) s += __shfl_xor_sync(0xffffffffu, s, off);
            float mu = s * (1.f/64.f);
            float xc0 = x0 - mu, xc1 = x1 - mu;
            float vv = xc0*xc0 + xc1*xc1;
#pragma unroll
            for (int off = 16; off; off >>= 1) vv += __shfl_xor_sync(0xffffffffu, vv, off);
            float rstd = rsqrtf(vv * (1.f/64.f) + EPSLN);
            float xh0 = xc0 * rstd, xh1 = xc1 * rstd;
            float w0 = w_s[lane], w1 = w_s[lane+32];
            float y0 = xh0*w0 + b_s[lane], y1 = xh1*w1 + b_s[lane+32];
            float dy0 = 2.f*(y0 - v_s[c][lane]);
            float dy1 = 2.f*(y1 - v_s[c][lane+32]);
            float wdy0 = dy0*w0, wdy1 = dy1*w1;
            float c1 = xh0*wdy0 + xh1*wdy1;
            float c2 = wdy0 + wdy1;
#pragma unroll
            for (int off = 16; off; off >>= 1) {
                c1 += __shfl_xor_sync(0xffffffffu, c1, off);
                c2 += __shfl_xor_sync(0xffffffffu, c2, off);
            }
            c1 *= (1.f/64.f); c2 *= (1.f/64.f);
            dkh_s[c][lane]    = (wdy0 - xh0*c1 - c2) * rstd;
            dkh_s[c][lane+32] = (wdy1 - xh1*c1 - c2) * rstd;
        }
        __syncthreads();

        // token scan: no barriers inside (state in registers)
        for (int c = 0; c < 16; c++) {
            float th = th_s[c], al = al_s[c], et = et_s[c];
            float dk = dkh_s[c][e];
            float oma = 1.f - al;
            float po = 0.f;
#pragma unroll
            for (int i = 0; i < 8; i++) {
                float gij = k_s[c][8*g + i] * dk;
                m[i] = et * m[i] - th * gij;
                S[i] = oma * S[i] + m[i];
                po += q_s[c][8*g + i] * S[i];
            }
            po += __shfl_xor_sync(0xffffffffu, po, 1);
            po += __shfl_xor_sync(0xffffffffu, po, 2);
            po += __shfl_xor_sync(0xffffffffu, po, 4);
            if (g == 0) o_s[c][e] = po;
        }
        __syncthreads();

        // final LN on o rows, write to g_o [b,t,c]
        {
            int c = wid;
            float x0 = o_s[c][lane], x1 = o_s[c][lane+32];
            float s = x0 + x1;
#pragma unroll
            for (int off = 16; off; off >>= 1) s += __shfl_xor_sync(0xffffffffu, s, off);
            float mu = s * (1.f/64.f);
            float xc0 = x0 - mu, xc1 = x1 - mu;
            float vv = xc0*xc0 + xc1*xc1;
#pragma unroll
            for (int off = 16; off; off >>= 1) vv += __shfl_xor_sync(0xffffffffu, vv, off);
            float rstd = rsqrtf(vv * (1.f/64.f) + EPSLN);
            int t = ci*16 + c;
            float* dst = g_o + ((size_t)b*Tdim + t)*Cdim + h*64;
            dst[lane]    = xc0*rstd*w_s[lane]    + b_s[lane];
            dst[lane+32] = xc1*rstd*w_s[lane+32] + b_s[lane+32];
        }
        // first __syncthreads of next iteration provides the needed barrier
    }
}

// ---------------------------------------------------------------------------
extern "C" void kernel_launch(void* const* d_in, const int* in_sizes, int n_in,
                              void* d_out, int out_size)
{
    const float* x       = (const float*)d_in[0];
    const float* W_attn  = (const float*)d_in[1];
    const float* b_attn  = (const float*)d_in[2];
    const float* W_param = (const float*)d_in[3];
    const float* b_param = (const float*)d_in[4];
    const float* W_proj  = (const float*)d_in[5];
    const float* b_proj  = (const float*)d_in[6];
    const float* w       = (const float*)d_in[7];
    const float* bb      = (const float*)d_in[8];
    float* out = (float*)d_out;

    gemm_qkv<<<dim3(24, 64), 256>>>(x, W_attn, b_attn);
    param_kernel<<<128, 256>>>(x, W_param, b_param);
    scan_kernel<<<64, 512>>>(w, bb);
    gemm_proj<<<dim3(8, 64), 256>>>(W_proj, b_proj, out);
}

// round 3
// speedup vs baseline: 1.0958x; 1.0958x over previous
#include <cuda_runtime.h>
#include <math.h>

typedef unsigned long long ull;

#define Bdim 4
#define Tdim 2048
#define Cdim 1024
#define Hdim 16
#define Ddim 64
#define CSdim 16
#define NTdim (Tdim/CSdim)          // 128 chunks
#define BTdim (Bdim*Tdim)           // 8192
#define BHT   (Bdim*Hdim*Tdim)      // 131072
#define EPSLN 1e-5f

// Scratch (allocation-free rule: __device__ globals)
__device__ float g_qkv[3][(size_t)BHT*Ddim];   // q,k,v in [b,h,t,d]
__device__ float g_param[3][BHT];              // theta,alpha,eta in [b,h,t]
__device__ float g_o[(size_t)BTdim*Cdim];      // o (post final LN) in [b,t,c]

// ---------------- packed f32x2 helpers (sm_103a FFMA2 path) ----------------
__device__ __forceinline__ ull pk(float lo, float hi) {
    ull r; asm("mov.b64 %0, {%1, %2};" : "=l"(r) : "f"(lo), "f"(hi)); return r;
}
__device__ __forceinline__ ull pk1(float v) {
    ull r; asm("mov.b64 %0, {%1, %1};" : "=l"(r) : "f"(v)); return r;
}
__device__ __forceinline__ ull fma2(ull a, ull b, ull c) {
    ull d; asm("fma.rn.f32x2 %0, %1, %2, %3;" : "=l"(d) : "l"(a), "l"(b), "l"(c)); return d;
}
__device__ __forceinline__ ull mul2(ull a, ull b) {
    ull d; asm("mul.rn.f32x2 %0, %1, %2;" : "=l"(d) : "l"(a), "l"(b)); return d;
}
__device__ __forceinline__ float2 upk(ull v) {
    float2 f; asm("mov.b64 {%0, %1}, %2;" : "=f"(f.x), "=f"(f.y) : "l"(v)); return f;
}

// ---------------- cp.async helpers ----------------
__device__ __forceinline__ void cpasync16(void* smem_dst, const void* gmem_src) {
    unsigned s = (unsigned)__cvta_generic_to_shared(smem_dst);
    asm volatile("cp.async.ca.shared.global [%0], [%1], 16;" :: "r"(s), "l"(gmem_src) : "memory");
}
__device__ __forceinline__ void cpcommit() {
    asm volatile("cp.async.commit_group;" ::: "memory");
}
__device__ __forceinline__ void cpwait1() {
    asm volatile("cp.async.wait_group 1;" ::: "memory");
}
__device__ __forceinline__ void cpwait0() {
    asm volatile("cp.async.wait_group 0;" ::: "memory");
}

// ---------------------------------------------------------------------------
// GEMM 128x128 tile, 256 threads, 8x8 micro-tile, FFMA2 inner loop,
// double-buffered smem.  MODE 1: qkv (scatter to g_qkv). MODE 0: proj.
// ---------------------------------------------------------------------------
template<int Nsz, int MODE>
__global__ __launch_bounds__(256, 2) void gemm128(const float* __restrict__ A,
                                                  const float* __restrict__ Bw,
                                                  const float* __restrict__ bias,
                                                  float* __restrict__ out)
{
    const int K = Cdim;
    __shared__ __align__(16) float As[2][8][128];
    __shared__ __align__(16) float Bs[2][8][128];
    int tid = threadIdx.x;
    int row0 = blockIdx.y * 128, col0 = blockIdx.x * 128;
    int aRow = tid >> 1, aCol = (tid & 1) << 2;
    int bRow = tid >> 5, bCol = (tid & 31) << 2;
    int tr = tid >> 4, tc = tid & 15;

    const float* Aeff = (MODE == 0) ? (const float*)g_o : A;

    ull acc[8][4];
#pragma unroll
    for (int i = 0; i < 8; i++)
#pragma unroll
        for (int j = 0; j < 4; j++) acc[i][j] = 0ull;

    const float* Aptr = Aeff + (size_t)(row0 + aRow) * K + aCol;
    const float* Bptr = Bw + (size_t)bRow * Nsz + col0 + bCol;

    // preload k-step 0
    float4 av = *(const float4*)Aptr;
    float4 bv = *(const float4*)Bptr;
    As[0][aCol+0][aRow] = av.x; As[0][aCol+1][aRow] = av.y;
    As[0][aCol+2][aRow] = av.z; As[0][aCol+3][aRow] = av.w;
    *(float4*)&Bs[0][bRow][bCol] = bv;
    __syncthreads();

    int buf = 0;
    for (int kt = 0; kt < K; kt += 8) {
        bool more = (kt + 8) < K;
        if (more) {
            av = *(const float4*)(Aptr + kt + 8);
            bv = *(const float4*)(Bptr + (size_t)(kt + 8) * Nsz);
        }
#pragma unroll
        for (int kk = 0; kk < 8; kk++) {
            float4 a0 = *(const float4*)&As[buf][kk][tr*8];
            float4 a1 = *(const float4*)&As[buf][kk][tr*8 + 4];
            float4 b0 = *(const float4*)&Bs[buf][kk][tc*8];
            float4 b1 = *(const float4*)&Bs[buf][kk][tc*8 + 4];
            ull bp0 = pk(b0.x, b0.y), bp1 = pk(b0.z, b0.w);
            ull bp2 = pk(b1.x, b1.y), bp3 = pk(b1.z, b1.w);
            float a[8] = {a0.x, a0.y, a0.z, a0.w, a1.x, a1.y, a1.z, a1.w};
#pragma unroll
            for (int i = 0; i < 8; i++) {
                ull ap = pk1(a[i]);
                acc[i][0] = fma2(ap, bp0, acc[i][0]);
                acc[i][1] = fma2(ap, bp1, acc[i][1]);
                acc[i][2] = fma2(ap, bp2, acc[i][2]);
                acc[i][3] = fma2(ap, bp3, acc[i][3]);
            }
        }
        if (more) {
            As[buf^1][aCol+0][aRow] = av.x; As[buf^1][aCol+1][aRow] = av.y;
            As[buf^1][aCol+2][aRow] = av.z; As[buf^1][aCol+3][aRow] = av.w;
            *(float4*)&Bs[buf^1][bRow][bCol] = bv;
            __syncthreads();
            buf ^= 1;
        }
    }

    // epilogue
#pragma unroll
    for (int i = 0; i < 8; i++) {
        int r = row0 + tr*8 + i;
#pragma unroll
        for (int jj = 0; jj < 2; jj++) {
            int col = col0 + tc*8 + jj*4;
            float2 p0 = upk(acc[i][jj*2 + 0]);
            float2 p1 = upk(acc[i][jj*2 + 1]);
            float4 v;
            v.x = p0.x + bias[col+0];
            v.y = p0.y + bias[col+1];
            v.z = p1.x + bias[col+2];
            v.w = p1.y + bias[col+3];
            if (MODE == 1) {
                int b = r >> 11, t = r & 2047;
                int kind = col >> 10;
                int cc = col & 1023;
                int h = cc >> 6, d = cc & 63;
                *(float4*)&g_qkv[kind][(((size_t)b*Hdim + h)*Tdim + t)*Ddim + d] = v;
            } else {
                *(float4*)(out + (size_t)r * Nsz + col) = v;
            }
        }
    }
}

// ---------------------------------------------------------------------------
// K2: p = sigmoid(x @ W_param + b_param) -> theta/alpha/eta [b,h,t]
// ---------------------------------------------------------------------------
__global__ __launch_bounds__(256) void param_kernel(const float* __restrict__ x,
                                                    const float* __restrict__ W,
                                                    const float* __restrict__ bias)
{
    __shared__ float xs[64][68];
    __shared__ float Ws[64][48];
    int tid = threadIdx.x;
    int row0 = blockIdx.x * 64;
    int r = tid >> 2, q = tid & 3;

    float acc[12];
#pragma unroll
    for (int j = 0; j < 12; j++) acc[j] = 0.f;

    for (int kt = 0; kt < Cdim; kt += 64) {
        int lr = tid >> 2;
        int lc0 = (tid & 3) * 4;
#pragma unroll
        for (int tt = 0; tt < 4; tt++) {
            float4 v = *(const float4*)(x + (size_t)(row0 + lr) * Cdim + kt + lc0 + tt*16);
            xs[lr][lc0 + tt*16 + 0] = v.x;
            xs[lr][lc0 + tt*16 + 1] = v.y;
            xs[lr][lc0 + tt*16 + 2] = v.z;
            xs[lr][lc0 + tt*16 + 3] = v.w;
        }
#pragma unroll
        for (int tt = 0; tt < 12; tt++) {
            int idx = tid + tt * 256;
            int wr = idx / 48, wc = idx % 48;
            Ws[wr][wc] = W[(size_t)(kt + wr) * 48 + wc];
        }
        __syncthreads();
#pragma unroll
        for (int kk = 0; kk < 64; kk++) {
            float xv = xs[r][kk];
#pragma unroll
            for (int j = 0; j < 12; j++) acc[j] += xv * Ws[kk][q + 4*j];
        }
        __syncthreads();
    }
    int grow = row0 + r;
    int b = grow / Tdim, t = grow % Tdim;
#pragma unroll
    for (int j = 0; j < 12; j++) {
        int col = q + 4*j;
        int h = col / 3, ii = col % 3;
        float v = acc[j] + bias[col];
        v = 1.f / (1.f + expf(-v));
        g_param[ii][((size_t)b*Hdim + h)*Tdim + t] = v;
    }
}

// ---------------------------------------------------------------------------
// K3: chunked Titans scan. One block per (b,h). 512 threads.
// Thread (e = tid>>3, g = tid&7) owns S[8g..8g+8)[e] as 4 packed f32x2 pairs.
// Double-buffered cp.async chunk prefetch (k,q,v + theta/alpha/eta).
// ---------------------------------------------------------------------------
#define CHUNK_F (CSdim*Ddim)     // 1024 floats per tensor per chunk
#define BUF_F   (3*CHUNK_F + 48) // + 16 th + 16 al + 16 et

__global__ __launch_bounds__(512) void scan_kernel(const float* __restrict__ w,
                                                   const float* __restrict__ bln)
{
    __shared__ __align__(16) float buf[2][BUF_F];
    __shared__ float kh_s[16][64], dkh_s[16][64], o_s[16][64];
    __shared__ float w_s[64], b_s[64];

    int tid  = threadIdx.x;
    int e    = tid >> 3, g = tid & 7;
    int lane = tid & 31, wid = tid >> 5;   // 16 warps, warp per chunk-row
    int bh = blockIdx.x;
    int b  = bh >> 4, h = bh & 15;

    const float* qg = g_qkv[0] + (size_t)bh * Tdim * Ddim;
    const float* kg = g_qkv[1] + (size_t)bh * Tdim * Ddim;
    const float* vg = g_qkv[2] + (size_t)bh * Tdim * Ddim;
    const float* thg = g_param[0] + (size_t)bh * Tdim;
    const float* alg = g_param[1] + (size_t)bh * Tdim;
    const float* etg = g_param[2] + (size_t)bh * Tdim;

    if (tid < 64) { w_s[tid] = w[h*64 + tid]; b_s[tid] = bln[h*64 + tid]; }

    ull S2[4], m2[4];
#pragma unroll
    for (int i = 0; i < 4; i++) { S2[i] = 0ull; m2[i] = 0ull; }

    // prefetch helper (inlined twice below): 780 float4 per chunk
#define PREFETCH(ci, dst)                                                     \
    do {                                                                      \
        int base4 = (ci) * (CHUNK_F/4);                                       \
        for (int idx = tid; idx < 780; idx += 512) {                          \
            if (idx < 256)                                                    \
                cpasync16((dst) + idx*4, (const float4*)kg + base4 + idx);    \
            else if (idx < 512)                                               \
                cpasync16((dst) + CHUNK_F + (idx-256)*4,                      \
                          (const float4*)qg + base4 + (idx-256));             \
            else if (idx < 768)                                               \
                cpasync16((dst) + 2*CHUNK_F + (idx-512)*4,                    \
                          (const float4*)vg + base4 + (idx-512));             \
            else if (idx < 772)                                               \
                cpasync16((dst) + 3*CHUNK_F + (idx-768)*4,                    \
                          (const float4*)(thg + (ci)*16) + (idx-768));        \
            else if (idx < 776)                                               \
                cpasync16((dst) + 3*CHUNK_F + 16 + (idx-772)*4,               \
                          (const float4*)(alg + (ci)*16) + (idx-772));        \
            else                                                              \
                cpasync16((dst) + 3*CHUNK_F + 32 + (idx-776)*4,               \
                          (const float4*)(etg + (ci)*16) + (idx-776));        \
        }                                                                     \
        cpcommit();                                                           \
    } while (0)

    PREFETCH(0, buf[0]);

    for (int ci = 0; ci < NTdim; ci++) {
        if (ci + 1 < NTdim) {
            PREFETCH(ci + 1, buf[(ci+1) & 1]);
            cpwait1();
        } else {
            cpwait0();
        }
        __syncthreads();

        float* Kp = buf[ci & 1];
        float* Qp = Kp + CHUNK_F;
        float* Vp = Kp + 2*CHUNK_F;
        float* TH = Kp + 3*CHUNK_F;
        float* AL = TH + 16;
        float* ET = TH + 32;

        // l2-normalize q,k rows (warp per row)
        {
            int c = wid;
            float k0 = Kp[c*64 + lane], k1 = Kp[c*64 + lane + 32];
            float q0 = Qp[c*64 + lane], q1 = Qp[c*64 + lane + 32];
            float sk = k0*k0 + k1*k1, sq = q0*q0 + q1*q1;
#pragma unroll
            for (int off = 16; off; off >>= 1) {
                sk += __shfl_xor_sync(0xffffffffu, sk, off);
                sq += __shfl_xor_sync(0xffffffffu, sq, off);
            }
            float rk = 1.f / fmaxf(sqrtf(sk), 1e-12f);
            float rq = 1.f / fmaxf(sqrtf(sq), 1e-12f);
            Kp[c*64 + lane] = k0*rk; Kp[c*64 + lane + 32] = k1*rk;
            Qp[c*64 + lane] = q0*rq; Qp[c*64 + lane + 32] = q1*rq;
        }
        __syncthreads();

        // kh = k @ S (packed partials + width-8 reduce)
#pragma unroll
        for (int c = 0; c < 16; c++) {
            float4 k0 = *(const float4*)&Kp[c*64 + 8*g];
            float4 k1 = *(const float4*)&Kp[c*64 + 8*g + 4];
            ull p2 = 0ull;
            p2 = fma2(pk(k0.x, k0.y), S2[0], p2);
            p2 = fma2(pk(k0.z, k0.w), S2[1], p2);
            p2 = fma2(pk(k1.x, k1.y), S2[2], p2);
            p2 = fma2(pk(k1.z, k1.w), S2[3], p2);
            float2 pf = upk(p2);
            float p = pf.x + pf.y;
            p += __shfl_xor_sync(0xffffffffu, p, 1);
            p += __shfl_xor_sync(0xffffffffu, p, 2);
            p += __shfl_xor_sync(0xffffffffu, p, 4);
            if (g == 0) kh_s[c][e] = p;
        }
        __syncthreads();

        // LN fwd + bwd per row: dkh = ln_bwd(kh, w, 2*(ln(kh)-v))
        {
            int c = wid;
            float x0 = kh_s[c][lane], x1 = kh_s[c][lane+32];
            float s = x0 + x1;
#pragma unroll
            for (int off = 16; off; off >>= 1) s += __shfl_xor_sync(0xffffffffu, s, off);
            float mu = s * (1.f/64.f);
            float xc0 = x0 - mu, xc1 = x1 - mu;
            float vv = xc0*xc0 + xc1*xc1;
#pragma unroll
            for (int off = 16; off; off >>= 1) vv += __shfl_xor_sync(0xffffffffu, vv, off);
            float rstd = rsqrtf(vv * (1.f/64.f) + EPSLN);
            float xh0 = xc0 * rstd, xh1 = xc1 * rstd;
            float w0 = w_s[lane], w1 = w_s[lane+32];
            float y0 = xh0*w0 + b_s[lane], y1 = xh1*w1 + b_s[lane+32];
            float dy0 = 2.f*(y0 - Vp[c*64 + lane]);
            float dy1 = 2.f*(y1 - Vp[c*64 + lane + 32]);
            float wdy0 = dy0*w0, wdy1 = dy1*w1;
            float c1 = xh0*wdy0 + xh1*wdy1;
            float c2 = wdy0 + wdy1;
#pragma unroll
            for (int off = 16; off; off >>= 1) {
                c1 += __shfl_xor_sync(0xffffffffu, c1, off);
                c2 += __shfl_xor_sync(0xffffffffu, c2, off);
            }
            c1 *= (1.f/64.f); c2 *= (1.f/64.f);
            dkh_s[c][lane]    = (wdy0 - xh0*c1 - c2) * rstd;
            dkh_s[c][lane+32] = (wdy1 - xh1*c1 - c2) * rstd;
        }
        __syncthreads();

        // token scan: state in packed registers, no barriers inside
#pragma unroll 4
        for (int c = 0; c < 16; c++) {
            float th = TH[c], al = AL[c], et = ET[c];
            float dk = dkh_s[c][e];
            float4 k0 = *(const float4*)&Kp[c*64 + 8*g];
            float4 k1 = *(const float4*)&Kp[c*64 + 8*g + 4];
            float4 q0 = *(const float4*)&Qp[c*64 + 8*g];
            float4 q1 = *(const float4*)&Qp[c*64 + 8*g + 4];
            ull kp[4] = {pk(k0.x,k0.y), pk(k0.z,k0.w), pk(k1.x,k1.y), pk(k1.z,k1.w)};
            ull qp[4] = {pk(q0.x,q0.y), pk(q0.z,q0.w), pk(q1.x,q1.y), pk(q1.z,q1.w)};
            ull et2  = pk1(et);
            ull oma2 = pk1(1.f - al);
            ull ntd2 = pk1(-th * dk);
            ull po2 = 0ull;
#pragma unroll
            for (int j = 0; j < 4; j++) {
                m2[j] = fma2(et2, m2[j], mul2(ntd2, kp[j]));
                S2[j] = fma2(oma2, S2[j], m2[j]);
                po2   = fma2(qp[j], S2[j], po2);
            }
            float2 pf = upk(po2);
            float po = pf.x + pf.y;
            po += __shfl_xor_sync(0xffffffffu, po, 1);
            po += __shfl_xor_sync(0xffffffffu, po, 2);
            po += __shfl_xor_sync(0xffffffffu, po, 4);
            if (g == 0) o_s[c][e] = po;
        }
        __syncthreads();

        // final LN on o rows, write to g_o [b,t,c]
        {
            int c = wid;
            float x0 = o_s[c][lane], x1 = o_s[c][lane+32];
            float s = x0 + x1;
#pragma unroll
            for (int off = 16; off; off >>= 1) s += __shfl_xor_sync(0xffffffffu, s, off);
            float mu = s * (1.f/64.f);
            float xc0 = x0 - mu, xc1 = x1 - mu;
            float vv = xc0*xc0 + xc1*xc1;
#pragma unroll
            for (int off = 16; off; off >>= 1) vv += __shfl_xor_sync(0xffffffffu, vv, off);
            float rstd = rsqrtf(vv * (1.f/64.f) + EPSLN);
            int t = ci*16 + c;
            float* dst = g_o + ((size_t)b*Tdim + t)*Cdim + h*64;
            dst[lane]    = xc0*rstd*w_s[lane]    + b_s[lane];
            dst[lane+32] = xc1*rstd*w_s[lane+32] + b_s[lane+32];
        }
        // loop-top __syncthreads covers o_s/kh_s reuse; buf WAR covered by
        // post-token-loop barrier (cp.async targets the buffer last read
        // before that barrier).
    }
#undef PREFETCH
}

// ---------------------------------------------------------------------------
extern "C" void kernel_launch(void* const* d_in, const int* in_sizes, int n_in,
                              void* d_out, int out_size)
{
    const float* x       = (const float*)d_in[0];
    const float* W_attn  = (const float*)d_in[1];
    const float* b_attn  = (const float*)d_in[2];
    const float* W_param = (const float*)d_in[3];
    const float* b_param = (const float*)d_in[4];
    const float* W_proj  = (const float*)d_in[5];
    const float* b_proj  = (const float*)d_in[6];
    const float* w       = (const float*)d_in[7];
    const float* bb      = (const float*)d_in[8];
    float* out = (float*)d_out;

    gemm128<3*Cdim, 1><<<dim3(24, 64), 256>>>(x, W_attn, b_attn, nullptr);
    param_kernel<<<128, 256>>>(x, W_param, b_param);
    scan_kernel<<<64, 512>>>(w, bb);
    gemm128<Cdim, 0><<<dim3(8, 64), 256>>>(nullptr, W_proj, b_proj, out);
}

// round 5
// speedup vs baseline: 1.5324x; 1.3985x over previous
#include <cuda_runtime.h>
#include <cuda_bf16.h>
#include <math.h>
#include <stdint.h>

typedef unsigned long long ull;

#define Bdim 4
#define Tdim 2048
#define Cdim 1024
#define Hdim 16
#define Ddim 64
#define CSdim 16
#define NTdim (Tdim/CSdim)          // 128 chunks
#define BTdim (Bdim*Tdim)           // 8192
#define BHT   (Bdim*Hdim*Tdim)      // 131072
#define EPSLN 1e-5f

// ---------------- device scratch (allocation-free rule) ----------------
__device__ float g_qkv[3][(size_t)BHT*Ddim];           // q,k,v  [b,h,t,d] fp32
__device__ float g_param[3][BHT];                      // theta/alpha/eta
__device__ __nv_bfloat16 g_xh[(size_t)BTdim*Cdim];     // x hi/lo bf16 [M,K]
__device__ __nv_bfloat16 g_xl[(size_t)BTdim*Cdim];
__device__ __nv_bfloat16 g_wah[(size_t)3*Cdim*Cdim];   // W_attn^T hi/lo [N,K]
__device__ __nv_bfloat16 g_wal[(size_t)3*Cdim*Cdim];
__device__ __nv_bfloat16 g_wph[(size_t)Cdim*Cdim];     // W_proj^T hi/lo [N,K]
__device__ __nv_bfloat16 g_wpl[(size_t)Cdim*Cdim];
__device__ __nv_bfloat16 g_oh[(size_t)BTdim*Cdim];     // scan output hi/lo [M,K]
__device__ __nv_bfloat16 g_ol[(size_t)BTdim*Cdim];

// ---------------- helpers ----------------
__device__ __forceinline__ uint32_t smem_u32(const void* p) {
    return (uint32_t)__cvta_generic_to_shared(p);
}
#define SWZ128(off) ((off) ^ (((off) >> 3) & 0x70))

__device__ __forceinline__ void cpasync16(uint32_t smem_dst, const void* gmem_src) {
    asm volatile("cp.async.ca.shared.global [%0], [%1], 16;" :: "r"(smem_dst), "l"(gmem_src) : "memory");
}
__device__ __forceinline__ void cpcommit()  { asm volatile("cp.async.commit_group;" ::: "memory"); }
__device__ __forceinline__ void cpwait1()   { asm volatile("cp.async.wait_group 1;" ::: "memory"); }
__device__ __forceinline__ void cpwait0()   { asm volatile("cp.async.wait_group 0;" ::: "memory"); }

__device__ __forceinline__ void ldmx4(uint32_t addr, uint32_t& r0, uint32_t& r1,
                                      uint32_t& r2, uint32_t& r3) {
    asm volatile("ldmatrix.sync.aligned.m8n8.x4.shared.b16 {%0,%1,%2,%3}, [%4];"
                 : "=r"(r0), "=r"(r1), "=r"(r2), "=r"(r3) : "r"(addr));
}
__device__ __forceinline__ void mma16816(float* c, uint32_t a0, uint32_t a1,
                                         uint32_t a2, uint32_t a3,
                                         uint32_t b0, uint32_t b1) {
    asm volatile("mma.sync.aligned.m16n8k16.row.col.f32.bf16.bf16.f32 "
                 "{%0,%1,%2,%3}, {%4,%5,%6,%7}, {%8,%9}, {%0,%1,%2,%3};"
                 : "+f"(c[0]), "+f"(c[1]), "+f"(c[2]), "+f"(c[3])
                 : "r"(a0), "r"(a1), "r"(a2), "r"(a3), "r"(b0), "r"(b1));
}

// ---------------------------------------------------------------------------
// convert_x: fp32 -> bf16 hi/lo split
// ---------------------------------------------------------------------------
__global__ __launch_bounds__(256) void convert_x(const float* __restrict__ x)
{
    size_t i = (size_t)blockIdx.x * 1024 + threadIdx.x * 4;
    float4 v = *(const float4*)(x + i);
    __nv_bfloat16 h0 = __float2bfloat16(v.x);
    __nv_bfloat16 h1 = __float2bfloat16(v.y);
    __nv_bfloat16 h2 = __float2bfloat16(v.z);
    __nv_bfloat16 h3 = __float2bfloat16(v.w);
    __nv_bfloat162* ph = (__nv_bfloat162*)(g_xh + i);
    __nv_bfloat162* pl = (__nv_bfloat162*)(g_xl + i);
    ph[0] = __nv_bfloat162(h0, h1);
    ph[1] = __nv_bfloat162(h2, h3);
    pl[0] = __nv_bfloat162(__float2bfloat16(v.x - __bfloat162float(h0)),
                           __float2bfloat16(v.y - __bfloat162float(h1)));
    pl[1] = __nv_bfloat162(__float2bfloat16(v.z - __bfloat162float(h2)),
                           __float2bfloat16(v.w - __bfloat162float(h3)));
}

// ---------------------------------------------------------------------------
// transpose + split W [K][N] fp32 -> WT hi/lo [N][K] bf16
// ---------------------------------------------------------------------------
__global__ __launch_bounds__(256) void transpose_w(const float* __restrict__ W,
                                                   __nv_bfloat16* __restrict__ WTh,
                                                   __nv_bfloat16* __restrict__ WTl,
                                                   int Nfull)
{
    __shared__ float tile[32][33];
    int n0 = blockIdx.x * 32, k0 = blockIdx.y * 32;
    int tx = threadIdx.x, ty = threadIdx.y;   // block (32,8)
#pragma unroll
    for (int i = 0; i < 32; i += 8)
        tile[ty + i][tx] = W[(size_t)(k0 + ty + i) * Nfull + n0 + tx];
    __syncthreads();
#pragma unroll
    for (int i = 0; i < 32; i += 8) {
        float v = tile[tx][ty + i];
        __nv_bfloat16 h = __float2bfloat16(v);
        WTh[(size_t)(n0 + ty + i) * Cdim + k0 + tx] = h;
        WTl[(size_t)(n0 + ty + i) * Cdim + k0 + tx] = __float2bfloat16(v - __bfloat162float(h));
    }
}

// ---------------------------------------------------------------------------
// HMMA GEMM: D[M,N] = 3-term bf16 split of A[M,K] @ B^T[N,K], fp32 accum.
// CTA 128x128 tile, 256 threads = 8 warps in 4(M) x 2(N).
// K processed in 48 chunks of 64 bf16 (3 split phases x 16).
// smem: per buffer A tile 128x64 bf16 (16KB, SW128 swizzle) + B tile same.
// MODE 1: scatter to g_qkv head layout. MODE 0: fp32 out.
// ---------------------------------------------------------------------------
#define NCHUNK 48
#define TILE_B 16384

template<int MODE>
__global__ __launch_bounds__(256) void mma_gemm(const __nv_bfloat16* __restrict__ Ah,
                                                const __nv_bfloat16* __restrict__ Al,
                                                const __nv_bfloat16* __restrict__ Bh,
                                                const __nv_bfloat16* __restrict__ Bl,
                                                const float* __restrict__ bias,
                                                float* __restrict__ out)
{
    extern __shared__ char smem[];
    __shared__ float bias_s[128];
    uint32_t base = (smem_u32(smem) + 1023) & ~1023u;
    uint32_t Aoff[2] = { base,              base + 2*TILE_B };
    uint32_t Boff[2] = { base + TILE_B,     base + 3*TILE_B };

    int tid = threadIdx.x;
    int wid = tid >> 5, lane = tid & 31;
    int wm = wid & 3, wn = wid >> 2;       // warp tile: rows wm*32..+32, cols wn*64..+64
    int row0 = blockIdx.y * 128, col0 = blockIdx.x * 128;

    if (tid < 128) bias_s[tid] = bias[col0 + tid];

    auto load_chunk = [&](int ci, int buf) {
        int p = ci >> 4;
        int kk0 = (ci & 15) * 64;
        const __nv_bfloat16* As = (p < 2)  ? Ah : Al;
        const __nv_bfloat16* Bs = (p == 1) ? Bl : Bh;
#pragma unroll
        for (int j = 0; j < 4; j++) {
            int id = tid + j * 256;
            int r = id >> 3, u = id & 7;
            uint32_t off = (uint32_t)(r * 128 + u * 16);
            cpasync16(Aoff[buf] + SWZ128(off), As + (size_t)(row0 + r) * Cdim + kk0 + u * 8);
        }
#pragma unroll
        for (int j = 0; j < 4; j++) {
            int id = tid + j * 256;
            int r = id >> 3, u = id & 7;
            uint32_t off = (uint32_t)(r * 128 + u * 16);
            cpasync16(Boff[buf] + SWZ128(off), Bs + (size_t)(col0 + r) * Cdim + kk0 + u * 8);
        }
        cpcommit();
    };

    float acc[2][8][4];
#pragma unroll
    for (int mt = 0; mt < 2; mt++)
#pragma unroll
        for (int nt = 0; nt < 8; nt++)
#pragma unroll
            for (int q = 0; q < 4; q++) acc[mt][nt][q] = 0.f;

    // per-thread ldmatrix row/byte components (within tile)
    int a_row = wm * 32 + (lane & 15);            // + mt*16
    int a_kb  = (lane >> 4) * 16;                 // + kk*32
    int b_row = wn * 64 + (lane & 7) + ((lane >> 4) << 3);  // + nt2*16
    int b_kb  = ((lane >> 3) & 1) * 16;           // + kk*32

    load_chunk(0, 0);

    for (int ci = 0; ci < NCHUNK; ci++) {
        int buf = ci & 1;
        if (ci + 1 < NCHUNK) { load_chunk(ci + 1, buf ^ 1); cpwait1(); }
        else                 { cpwait0(); }
        __syncthreads();

#pragma unroll
        for (int kk = 0; kk < 4; kk++) {
            uint32_t a[2][4];
#pragma unroll
            for (int mt = 0; mt < 2; mt++) {
                uint32_t off = (uint32_t)((a_row + mt*16) * 128 + kk*32 + a_kb);
                ldmx4(Aoff[buf] + SWZ128(off), a[mt][0], a[mt][1], a[mt][2], a[mt][3]);
            }
            uint32_t bfr[4][4];
#pragma unroll
            for (int nt2 = 0; nt2 < 4; nt2++) {
                uint32_t off = (uint32_t)((b_row + nt2*16) * 128 + kk*32 + b_kb);
                ldmx4(Boff[buf] + SWZ128(off), bfr[nt2][0], bfr[nt2][1], bfr[nt2][2], bfr[nt2][3]);
            }
#pragma unroll
            for (int mt = 0; mt < 2; mt++)
#pragma unroll
                for (int nt = 0; nt < 8; nt++) {
                    int nt2 = nt >> 1, hi = (nt & 1) << 1;
                    mma16816(acc[mt][nt], a[mt][0], a[mt][1], a[mt][2], a[mt][3],
                             bfr[nt2][hi], bfr[nt2][hi + 1]);
                }
        }
        __syncthreads();
    }

    // epilogue: thread (lane) covers rows lane>>2 (+8), cols (lane&3)*2 (+1)
    int rbase = row0 + wm * 32 + (lane >> 2);
    if (MODE == 1) {
        int gcb = col0 + wn * 64;
        int kind = gcb >> 10;
        int h2 = (gcb & 1023) >> 6;
#pragma unroll
        for (int mt = 0; mt < 2; mt++) {
#pragma unroll
            for (int half = 0; half < 2; half++) {
                int r = rbase + mt*16 + half*8;
                int b = r >> 11, t = r & 2047;
                float* dst = &g_qkv[kind][(((size_t)b*Hdim + h2)*Tdim + t)*Ddim];
#pragma unroll
                for (int nt = 0; nt < 8; nt++) {
                    int cd = nt*8 + (lane & 3)*2;
                    float2 v;
                    v.x = acc[mt][nt][half*2 + 0] + bias_s[wn*64 + cd + 0];
                    v.y = acc[mt][nt][half*2 + 1] + bias_s[wn*64 + cd + 1];
                    *(float2*)(dst + cd) = v;
                }
            }
        }
    } else {
#pragma unroll
        for (int mt = 0; mt < 2; mt++) {
#pragma unroll
            for (int half = 0; half < 2; half++) {
                int r = rbase + mt*16 + half*8;
                float* dst = out + (size_t)r * Cdim + col0 + wn*64;
#pragma unroll
                for (int nt = 0; nt < 8; nt++) {
                    int cd = nt*8 + (lane & 3)*2;
                    float2 v;
                    v.x = acc[mt][nt][half*2 + 0] + bias_s[wn*64 + cd + 0];
                    v.y = acc[mt][nt][half*2 + 1] + bias_s[wn*64 + cd + 1];
                    *(float2*)(dst + cd) = v;
                }
            }
        }
    }
}

// ---------------------------------------------------------------------------
// K2: p = sigmoid(x @ W_param + b_param)
// ---------------------------------------------------------------------------
__global__ __launch_bounds__(256) void param_kernel(const float* __restrict__ x,
                                                    const float* __restrict__ W,
                                                    const float* __restrict__ bias)
{
    __shared__ float xs[64][68];
    __shared__ float Ws[64][48];
    int tid = threadIdx.x;
    int row0 = blockIdx.x * 64;
    int r = tid >> 2, q = tid & 3;

    float acc[12];
#pragma unroll
    for (int j = 0; j < 12; j++) acc[j] = 0.f;

    for (int kt = 0; kt < Cdim; kt += 64) {
        int lr = tid >> 2;
        int lc0 = (tid & 3) * 4;
#pragma unroll
        for (int tt = 0; tt < 4; tt++) {
            float4 v = *(const float4*)(x + (size_t)(row0 + lr) * Cdim + kt + lc0 + tt*16);
            xs[lr][lc0 + tt*16 + 0] = v.x;
            xs[lr][lc0 + tt*16 + 1] = v.y;
            xs[lr][lc0 + tt*16 + 2] = v.z;
            xs[lr][lc0 + tt*16 + 3] = v.w;
        }
#pragma unroll
        for (int tt = 0; tt < 12; tt++) {
            int idx = tid + tt * 256;
            int wr = idx / 48, wc = idx % 48;
            Ws[wr][wc] = W[(size_t)(kt + wr) * 48 + wc];
        }
        __syncthreads();
#pragma unroll
        for (int kk = 0; kk < 64; kk++) {
            float xv = xs[r][kk];
#pragma unroll
            for (int j = 0; j < 12; j++) acc[j] += xv * Ws[kk][q + 4*j];
        }
        __syncthreads();
    }
    int grow = row0 + r;
    int b = grow / Tdim, t = grow % Tdim;
#pragma unroll
    for (int j = 0; j < 12; j++) {
        int col = q + 4*j;
        int h = col / 3, ii = col % 3;
        float v = acc[j] + bias[col];
        v = 1.f / (1.f + expf(-v));
        g_param[ii][((size_t)b*Hdim + h)*Tdim + t] = v;
    }
}

// ---------------------------------------------------------------------------
// K3: chunked Titans scan (emits bf16 hi/lo for proj GEMM)
// ---------------------------------------------------------------------------
__device__ __forceinline__ ull pk(float lo, float hi) {
    ull r; asm("mov.b64 %0, {%1, %2};" : "=l"(r) : "f"(lo), "f"(hi)); return r;
}
__device__ __forceinline__ ull pk1(float v) {
    ull r; asm("mov.b64 %0, {%1, %1};" : "=l"(r) : "f"(v)); return r;
}
__device__ __forceinline__ ull fma2(ull a, ull b, ull c) {
    ull d; asm("fma.rn.f32x2 %0, %1, %2, %3;" : "=l"(d) : "l"(a), "l"(b), "l"(c)); return d;
}
__device__ __forceinline__ ull mul2(ull a, ull b) {
    ull d; asm("mul.rn.f32x2 %0, %1, %2;" : "=l"(d) : "l"(a), "l"(b)); return d;
}
__device__ __forceinline__ float2 upk(ull v) {
    float2 f; asm("mov.b64 {%0, %1}, %2;" : "=f"(f.x), "=f"(f.y) : "l"(v)); return f;
}

#define CHUNK_F (CSdim*Ddim)
#define BUF_F   (3*CHUNK_F + 48)

__global__ __launch_bounds__(512) void scan_kernel(const float* __restrict__ w,
                                                   const float* __restrict__ bln)
{
    __shared__ __align__(16) float buf[2][BUF_F];
    __shared__ float kh_s[16][64], dkh_s[16][64], o_s[16][64];
    __shared__ float w_s[64], b_s[64];

    int tid  = threadIdx.x;
    int e    = tid >> 3, g = tid & 7;
    int lane = tid & 31, wid = tid >> 5;
    int bh = blockIdx.x;
    int b  = bh >> 4, h = bh & 15;

    const float* qg = g_qkv[0] + (size_t)bh * Tdim * Ddim;
    const float* kg = g_qkv[1] + (size_t)bh * Tdim * Ddim;
    const float* vg = g_qkv[2] + (size_t)bh * Tdim * Ddim;
    const float* thg = g_param[0] + (size_t)bh * Tdim;
    const float* alg = g_param[1] + (size_t)bh * Tdim;
    const float* etg = g_param[2] + (size_t)bh * Tdim;

    if (tid < 64) { w_s[tid] = w[h*64 + tid]; b_s[tid] = bln[h*64 + tid]; }

    ull S2[4], m2[4];
#pragma unroll
    for (int i = 0; i < 4; i++) { S2[i] = 0ull; m2[i] = 0ull; }

#define PREFETCH(ci, dst)                                                     \
    do {                                                                      \
        int base4 = (ci) * (CHUNK_F/4);                                       \
        for (int idx = tid; idx < 780; idx += 512) {                          \
            if (idx < 256)                                                    \
                cpasync16(smem_u32((dst) + idx*4), (const float4*)kg + base4 + idx); \
            else if (idx < 512)                                               \
                cpasync16(smem_u32((dst) + CHUNK_F + (idx-256)*4),            \
                          (const float4*)qg + base4 + (idx-256));             \
            else if (idx < 768)                                               \
                cpasync16(smem_u32((dst) + 2*CHUNK_F + (idx-512)*4),          \
                          (const float4*)vg + base4 + (idx-512));             \
            else if (idx < 772)                                               \
                cpasync16(smem_u32((dst) + 3*CHUNK_F + (idx-768)*4),          \
                          (const float4*)(thg + (ci)*16) + (idx-768));        \
            else if (idx < 776)                                               \
                cpasync16(smem_u32((dst) + 3*CHUNK_F + 16 + (idx-772)*4),     \
                          (const float4*)(alg + (ci)*16) + (idx-772));        \
            else                                                              \
                cpasync16(smem_u32((dst) + 3*CHUNK_F + 32 + (idx-776)*4),     \
                          (const float4*)(etg + (ci)*16) + (idx-776));        \
        }                                                                     \
        cpcommit();                                                           \
    } while (0)

    PREFETCH(0, buf[0]);

    for (int ci = 0; ci < NTdim; ci++) {
        if (ci + 1 < NTdim) {
            PREFETCH(ci + 1, buf[(ci+1) & 1]);
            cpwait1();
        } else {
            cpwait0();
        }
        __syncthreads();

        float* Kp = buf[ci & 1];
        float* Qp = Kp + CHUNK_F;
        float* Vp = Kp + 2*CHUNK_F;
        float* TH = Kp + 3*CHUNK_F;
        float* AL = TH + 16;
        float* ET = TH + 32;

        {
            int c = wid;
            float k0 = Kp[c*64 + lane], k1 = Kp[c*64 + lane + 32];
            float q0 = Qp[c*64 + lane], q1 = Qp[c*64 + lane + 32];
            float sk = k0*k0 + k1*k1, sq = q0*q0 + q1*q1;
#pragma unroll
            for (int off = 16; off; off >>= 1) {
                sk += __shfl_xor_sync(0xffffffffu, sk, off);
                sq += __shfl_xor_sync(0xffffffffu, sq, off);
            }
            float rk = 1.f / fmaxf(sqrtf(sk), 1e-12f);
            float rq = 1.f / fmaxf(sqrtf(sq), 1e-12f);
            Kp[c*64 + lane] = k0*rk; Kp[c*64 + lane + 32] = k1*rk;
            Qp[c*64 + lane] = q0*rq; Qp[c*64 + lane + 32] = q1*rq;
        }
        __syncthreads();

#pragma unroll
        for (int c = 0; c < 16; c++) {
            float4 k0 = *(const float4*)&Kp[c*64 + 8*g];
            float4 k1 = *(const float4*)&Kp[c*64 + 8*g + 4];
            ull p2 = 0ull;
            p2 = fma2(pk(k0.x, k0.y), S2[0], p2);
            p2 = fma2(pk(k0.z, k0.w), S2[1], p2);
            p2 = fma2(pk(k1.x, k1.y), S2[2], p2);
            p2 = fma2(pk(k1.z, k1.w), S2[3], p2);
            float2 pf = upk(p2);
            float p = pf.x + pf.y;
            p += __shfl_xor_sync(0xffffffffu, p, 1);
            p += __shfl_xor_sync(0xffffffffu, p, 2);
            p += __shfl_xor_sync(0xffffffffu, p, 4);
            if (g == 0) kh_s[c][e] = p;
        }
        __syncthreads();

        {
            int c = wid;
            float x0 = kh_s[c][lane], x1 = kh_s[c][lane+32];
            float s = x0 + x1;
#pragma unroll
            for (int off = 16; off; off >>= 1) s += __shfl_xor_sync(0xffffffffu, s, off);
            float mu = s * (1.f/64.f);
            float xc0 = x0 - mu, xc1 = x1 - mu;
            float vv = xc0*xc0 + xc1*xc1;
#pragma unroll
            for (int off = 16; off; off >>= 1) vv += __shfl_xor_sync(0xffffffffu, vv, off);
            float rstd = rsqrtf(vv * (1.f/64.f) + EPSLN);
            float xh0 = xc0 * rstd, xh1 = xc1 * rstd;
            float w0 = w_s[lane], w1 = w_s[lane+32];
            float y0 = xh0*w0 + b_s[lane], y1 = xh1*w1 + b_s[lane+32];
            float dy0 = 2.f*(y0 - Vp[c*64 + lane]);
            float dy1 = 2.f*(y1 - Vp[c*64 + lane + 32]);
            float wdy0 = dy0*w0, wdy1 = dy1*w1;
            float c1 = xh0*wdy0 + xh1*wdy1;
            float c2 = wdy0 + wdy1;
#pragma unroll
            for (int off = 16; off; off >>= 1) {
                c1 += __shfl_xor_sync(0xffffffffu, c1, off);
                c2 += __shfl_xor_sync(0xffffffffu, c2, off);
            }
            c1 *= (1.f/64.f); c2 *= (1.f/64.f);
            dkh_s[c][lane]    = (wdy0 - xh0*c1 - c2) * rstd;
            dkh_s[c][lane+32] = (wdy1 - xh1*c1 - c2) * rstd;
        }
        __syncthreads();

#pragma unroll 4
        for (int c = 0; c < 16; c++) {
            float th = TH[c], al = AL[c], et = ET[c];
            float dk = dkh_s[c][e];
            float4 k0 = *(const float4*)&Kp[c*64 + 8*g];
            float4 k1 = *(const float4*)&Kp[c*64 + 8*g + 4];
            float4 q0 = *(const float4*)&Qp[c*64 + 8*g];
            float4 q1 = *(const float4*)&Qp[c*64 + 8*g + 4];
            ull kp[4] = {pk(k0.x,k0.y), pk(k0.z,k0.w), pk(k1.x,k1.y), pk(k1.z,k1.w)};
            ull qp[4] = {pk(q0.x,q0.y), pk(q0.z,q0.w), pk(q1.x,q1.y), pk(q1.z,q1.w)};
            ull et2  = pk1(et);
            ull oma2 = pk1(1.f - al);
            ull ntd2 = pk1(-th * dk);
            ull po2 = 0ull;
#pragma unroll
            for (int j = 0; j < 4; j++) {
                m2[j] = fma2(et2, m2[j], mul2(ntd2, kp[j]));
                S2[j] = fma2(oma2, S2[j], m2[j]);
                po2   = fma2(qp[j], S2[j], po2);
            }
            float2 pf = upk(po2);
            float po = pf.x + pf.y;
            po += __shfl_xor_sync(0xffffffffu, po, 1);
            po += __shfl_xor_sync(0xffffffffu, po, 2);
            po += __shfl_xor_sync(0xffffffffu, po, 4);
            if (g == 0) o_s[c][e] = po;
        }
        __syncthreads();

        {
            int c = wid;
            float x0 = o_s[c][lane], x1 = o_s[c][lane+32];
            float s = x0 + x1;
#pragma unroll
            for (int off = 16; off; off >>= 1) s += __shfl_xor_sync(0xffffffffu, s, off);
            float mu = s * (1.f/64.f);
            float xc0 = x0 - mu, xc1 = x1 - mu;
            float vv = xc0*xc0 + xc1*xc1;
#pragma unroll
            for (int off = 16; off; off >>= 1) vv += __shfl_xor_sync(0xffffffffu, vv, off);
            float rstd = rsqrtf(vv * (1.f/64.f) + EPSLN);
            int t = ci*16 + c;
            size_t base = ((size_t)b*Tdim + t)*Cdim + h*64;
            float v0 = xc0*rstd*w_s[lane]    + b_s[lane];
            float v1 = xc1*rstd*w_s[lane+32] + b_s[lane+32];
            __nv_bfloat16 h0 = __float2bfloat16(v0);
            __nv_bfloat16 h1 = __float2bfloat16(v1);
            g_oh[base + lane]      = h0;
            g_oh[base + lane + 32] = h1;
            g_ol[base + lane]      = __float2bfloat16(v0 - __bfloat162float(h0));
            g_ol[base + lane + 32] = __float2bfloat16(v1 - __bfloat162float(h1));
        }
    }
#undef PREFETCH
}

// ---------------------------------------------------------------------------
extern "C" void kernel_launch(void* const* d_in, const int* in_sizes, int n_in,
                              void* d_out, int out_size)
{
    const float* x       = (const float*)d_in[0];
    const float* W_attn  = (const float*)d_in[1];
    const float* b_attn  = (const float*)d_in[2];
    const float* W_param = (const float*)d_in[3];
    const float* b_param = (const float*)d_in[4];
    const float* W_proj  = (const float*)d_in[5];
    const float* b_proj  = (const float*)d_in[6];
    const float* w       = (const float*)d_in[7];
    const float* bb      = (const float*)d_in[8];
    float* out = (float*)d_out;

    const int SMEM_MMA = 1024 + 4*TILE_B;   // 64KB tiles + align slack
    cudaFuncSetAttribute(mma_gemm<1>, cudaFuncAttributeMaxDynamicSharedMemorySize, SMEM_MMA);
    cudaFuncSetAttribute(mma_gemm<0>, cudaFuncAttributeMaxDynamicSharedMemorySize, SMEM_MMA);

    __nv_bfloat16 *xh, *xl, *wah, *wal, *wph, *wpl, *oh, *ol;
    cudaGetSymbolAddress((void**)&xh,  g_xh);
    cudaGetSymbolAddress((void**)&xl,  g_xl);
    cudaGetSymbolAddress((void**)&wah, g_wah);
    cudaGetSymbolAddress((void**)&wal, g_wal);
    cudaGetSymbolAddress((void**)&wph, g_wph);
    cudaGetSymbolAddress((void**)&wpl, g_wpl);
    cudaGetSymbolAddress((void**)&oh,  g_oh);
    cudaGetSymbolAddress((void**)&ol,  g_ol);

    convert_x<<<(BTdim*Cdim)/1024, 256>>>(x);
    transpose_w<<<dim3(96, 32), dim3(32, 8)>>>(W_attn, wah, wal, 3*Cdim);
    transpose_w<<<dim3(32, 32), dim3(32, 8)>>>(W_proj, wph, wpl, Cdim);
    param_kernel<<<128, 256>>>(x, W_param, b_param);

    mma_gemm<1><<<dim3(24, 64), 256, SMEM_MMA>>>(xh, xl, wah, wal, b_attn, nullptr);
    scan_kernel<<<64, 512>>>(w, bb);
    mma_gemm<0><<<dim3(8, 64), 256, SMEM_MMA>>>(oh, ol, wph, wpl, b_proj, out);
}

// round 6
// speedup vs baseline: 1.8352x; 1.1975x over previous
#include <cuda_runtime.h>
#include <cuda_fp16.h>
#include <math.h>
#include <stdint.h>

typedef unsigned long long ull;

#define Bdim 4
#define Tdim 2048
#define Cdim 1024
#define Hdim 16
#define Ddim 64
#define CSdim 16
#define NTdim (Tdim/CSdim)          // 128 chunks
#define BTdim (Bdim*Tdim)           // 8192
#define BHT   (Bdim*Hdim*Tdim)      // 131072
#define EPSLN 1e-5f

// ---------------- device scratch (allocation-free rule) ----------------
__device__ float g_qkv[3][(size_t)BHT*Ddim];           // q,k,v  [b,h,t,d] fp32
__device__ float g_param[3][BHT];                      // theta/alpha/eta
__device__ __half g_xh[(size_t)BTdim*Cdim];            // x hi/lo fp16 [M,K]
__device__ __half g_xl[(size_t)BTdim*Cdim];
__device__ __half g_wah[(size_t)3*Cdim*Cdim];          // W_attn^T fp16 [N,K]
__device__ __half g_wph[(size_t)Cdim*Cdim];            // W_proj^T fp16 [N,K]
__device__ __half g_oh[(size_t)BTdim*Cdim];            // scan out hi/lo fp16 [M,K]
__device__ __half g_ol[(size_t)BTdim*Cdim];

// ---------------- helpers ----------------
__device__ __forceinline__ uint32_t smem_u32(const void* p) {
    return (uint32_t)__cvta_generic_to_shared(p);
}
#define SWZ128(off) ((off) ^ (((off) >> 3) & 0x70))

__device__ __forceinline__ void cpasync16(uint32_t smem_dst, const void* gmem_src) {
    asm volatile("cp.async.ca.shared.global [%0], [%1], 16;" :: "r"(smem_dst), "l"(gmem_src) : "memory");
}
__device__ __forceinline__ void cpcommit()  { asm volatile("cp.async.commit_group;" ::: "memory"); }
__device__ __forceinline__ void cpwait1()   { asm volatile("cp.async.wait_group 1;" ::: "memory"); }
__device__ __forceinline__ void cpwait0()   { asm volatile("cp.async.wait_group 0;" ::: "memory"); }

__device__ __forceinline__ void ldmx4(uint32_t addr, uint32_t& r0, uint32_t& r1,
                                      uint32_t& r2, uint32_t& r3) {
    asm volatile("ldmatrix.sync.aligned.m8n8.x4.shared.b16 {%0,%1,%2,%3}, [%4];"
                 : "=r"(r0), "=r"(r1), "=r"(r2), "=r"(r3) : "r"(addr));
}
__device__ __forceinline__ void mma16816(float* c, uint32_t a0, uint32_t a1,
                                         uint32_t a2, uint32_t a3,
                                         uint32_t b0, uint32_t b1) {
    asm volatile("mma.sync.aligned.m16n8k16.row.col.f32.f16.f16.f32 "
                 "{%0,%1,%2,%3}, {%4,%5,%6,%7}, {%8,%9}, {%0,%1,%2,%3};"
                 : "+f"(c[0]), "+f"(c[1]), "+f"(c[2]), "+f"(c[3])
                 : "r"(a0), "r"(a1), "r"(a2), "r"(a3), "r"(b0), "r"(b1));
}

// ---------------------------------------------------------------------------
// convert_x: fp32 -> fp16 hi/lo split
// ---------------------------------------------------------------------------
__global__ __launch_bounds__(256) void convert_x(const float* __restrict__ x)
{
    size_t i = (size_t)blockIdx.x * 1024 + threadIdx.x * 4;
    float4 v = *(const float4*)(x + i);
    __half h0 = __float2half(v.x);
    __half h1 = __float2half(v.y);
    __half h2 = __float2half(v.z);
    __half h3 = __float2half(v.w);
    __half2* ph = (__half2*)(g_xh + i);
    __half2* pl = (__half2*)(g_xl + i);
    ph[0] = __half2(h0, h1);
    ph[1] = __half2(h2, h3);
    pl[0] = __half2(__float2half(v.x - __half2float(h0)),
                    __float2half(v.y - __half2float(h1)));
    pl[1] = __half2(__float2half(v.z - __half2float(h2)),
                    __float2half(v.w - __half2float(h3)));
}

// ---------------------------------------------------------------------------
// transpose W [K][N] fp32 -> WT fp16 [N][K]
// ---------------------------------------------------------------------------
__global__ __launch_bounds__(256) void transpose_w(const float* __restrict__ W,
                                                   __half* __restrict__ WTh,
                                                   int Nfull)
{
    __shared__ float tile[32][33];
    int n0 = blockIdx.x * 32, k0 = blockIdx.y * 32;
    int tx = threadIdx.x, ty = threadIdx.y;   // block (32,8)
#pragma unroll
    for (int i = 0; i < 32; i += 8)
        tile[ty + i][tx] = W[(size_t)(k0 + ty + i) * Nfull + n0 + tx];
    __syncthreads();
#pragma unroll
    for (int i = 0; i < 32; i += 8)
        WTh[(size_t)(n0 + ty + i) * Cdim + k0 + tx] = __float2half(tile[tx][ty + i]);
}

// ---------------------------------------------------------------------------
// HMMA GEMM: D = Ah@B^T + Al@B^T (fp16, fp32 accum). CTA 128x128 tile,
// 256 threads = 8 warps (4M x 2N). 32 K-chunks of 64 (2 phases x 16).
// MODE 1: scatter to g_qkv. MODE 0: fp32 out.
// ---------------------------------------------------------------------------
#define NCHUNK 32
#define TILE_B 16384

template<int MODE>
__global__ __launch_bounds__(256) void mma_gemm(const __half* __restrict__ Ah,
                                                const __half* __restrict__ Al,
                                                const __half* __restrict__ Bh,
                                                const float* __restrict__ bias,
                                                float* __restrict__ out)
{
    extern __shared__ char smem[];
    __shared__ float bias_s[128];
    uint32_t base = (smem_u32(smem) + 1023) & ~1023u;
    uint32_t Aoff[2] = { base,              base + 2*TILE_B };
    uint32_t Boff[2] = { base + TILE_B,     base + 3*TILE_B };

    int tid = threadIdx.x;
    int wid = tid >> 5, lane = tid & 31;
    int wm = wid & 3, wn = wid >> 2;
    int row0 = blockIdx.y * 128, col0 = blockIdx.x * 128;

    if (tid < 128) bias_s[tid] = bias[col0 + tid];

    auto load_chunk = [&](int ci, int buf) {
        int p = ci >> 4;
        int kk0 = (ci & 15) * 64;
        const __half* As = p ? Al : Ah;
#pragma unroll
        for (int j = 0; j < 4; j++) {
            int id = tid + j * 256;
            int r = id >> 3, u = id & 7;
            uint32_t off = (uint32_t)(r * 128 + u * 16);
            cpasync16(Aoff[buf] + SWZ128(off), As + (size_t)(row0 + r) * Cdim + kk0 + u * 8);
        }
#pragma unroll
        for (int j = 0; j < 4; j++) {
            int id = tid + j * 256;
            int r = id >> 3, u = id & 7;
            uint32_t off = (uint32_t)(r * 128 + u * 16);
            cpasync16(Boff[buf] + SWZ128(off), Bh + (size_t)(col0 + r) * Cdim + kk0 + u * 8);
        }
        cpcommit();
    };

    float acc[2][8][4];
#pragma unroll
    for (int mt = 0; mt < 2; mt++)
#pragma unroll
        for (int nt = 0; nt < 8; nt++)
#pragma unroll
            for (int q = 0; q < 4; q++) acc[mt][nt][q] = 0.f;

    int a_row = wm * 32 + (lane & 15);
    int a_kb  = (lane >> 4) * 16;
    int b_row = wn * 64 + (lane & 7) + ((lane >> 4) << 3);
    int b_kb  = ((lane >> 3) & 1) * 16;

    load_chunk(0, 0);

    for (int ci = 0; ci < NCHUNK; ci++) {
        int buf = ci & 1;
        if (ci + 1 < NCHUNK) { load_chunk(ci + 1, buf ^ 1); cpwait1(); }
        else                 { cpwait0(); }
        __syncthreads();

#pragma unroll
        for (int kk = 0; kk < 4; kk++) {
            uint32_t a[2][4];
#pragma unroll
            for (int mt = 0; mt < 2; mt++) {
                uint32_t off = (uint32_t)((a_row + mt*16) * 128 + kk*32 + a_kb);
                ldmx4(Aoff[buf] + SWZ128(off), a[mt][0], a[mt][1], a[mt][2], a[mt][3]);
            }
            uint32_t bfr[4][4];
#pragma unroll
            for (int nt2 = 0; nt2 < 4; nt2++) {
                uint32_t off = (uint32_t)((b_row + nt2*16) * 128 + kk*32 + b_kb);
                ldmx4(Boff[buf] + SWZ128(off), bfr[nt2][0], bfr[nt2][1], bfr[nt2][2], bfr[nt2][3]);
            }
#pragma unroll
            for (int mt = 0; mt < 2; mt++)
#pragma unroll
                for (int nt = 0; nt < 8; nt++) {
                    int nt2 = nt >> 1, hi = (nt & 1) << 1;
                    mma16816(acc[mt][nt], a[mt][0], a[mt][1], a[mt][2], a[mt][3],
                             bfr[nt2][hi], bfr[nt2][hi + 1]);
                }
        }
        __syncthreads();
    }

    int rbase = row0 + wm * 32 + (lane >> 2);
    if (MODE == 1) {
        int gcb = col0 + wn * 64;
        int kind = gcb >> 10;
        int h2 = (gcb & 1023) >> 6;
#pragma unroll
        for (int mt = 0; mt < 2; mt++) {
#pragma unroll
            for (int half = 0; half < 2; half++) {
                int r = rbase + mt*16 + half*8;
                int b = r >> 11, t = r & 2047;
                float* dst = &g_qkv[kind][(((size_t)b*Hdim + h2)*Tdim + t)*Ddim];
#pragma unroll
                for (int nt = 0; nt < 8; nt++) {
                    int cd = nt*8 + (lane & 3)*2;
                    float2 v;
                    v.x = acc[mt][nt][half*2 + 0] + bias_s[wn*64 + cd + 0];
                    v.y = acc[mt][nt][half*2 + 1] + bias_s[wn*64 + cd + 1];
                    *(float2*)(dst + cd) = v;
                }
            }
        }
    } else {
#pragma unroll
        for (int mt = 0; mt < 2; mt++) {
#pragma unroll
            for (int half = 0; half < 2; half++) {
                int r = rbase + mt*16 + half*8;
                float* dst = out + (size_t)r * Cdim + col0 + wn*64;
#pragma unroll
                for (int nt = 0; nt < 8; nt++) {
                    int cd = nt*8 + (lane & 3)*2;
                    float2 v;
                    v.x = acc[mt][nt][half*2 + 0] + bias_s[wn*64 + cd + 0];
                    v.y = acc[mt][nt][half*2 + 1] + bias_s[wn*64 + cd + 1];
                    *(float2*)(dst + cd) = v;
                }
            }
        }
    }
}

// ---------------------------------------------------------------------------
// K2: p = sigmoid(x @ W_param + b_param). 256 blocks x 32 rows.
// ---------------------------------------------------------------------------
__global__ __launch_bounds__(256) void param_kernel(const float* __restrict__ x,
                                                    const float* __restrict__ W,
                                                    const float* __restrict__ bias)
{
    __shared__ float xs[32][68];
    __shared__ float Ws[64][48];
    int tid = threadIdx.x;
    int row0 = blockIdx.x * 32;
    int r = tid >> 3, q = tid & 7;          // 32 rows x 8 col-groups (6 cols each)

    float acc[6];
#pragma unroll
    for (int j = 0; j < 6; j++) acc[j] = 0.f;

    for (int kt = 0; kt < Cdim; kt += 64) {
        int lr = tid >> 3;
        int lc0 = (tid & 7) * 8;
#pragma unroll
        for (int tt = 0; tt < 2; tt++) {
            float4 v = *(const float4*)(x + (size_t)(row0 + lr) * Cdim + kt + lc0 + tt*4);
            xs[lr][lc0 + tt*4 + 0] = v.x;
            xs[lr][lc0 + tt*4 + 1] = v.y;
            xs[lr][lc0 + tt*4 + 2] = v.z;
            xs[lr][lc0 + tt*4 + 3] = v.w;
        }
#pragma unroll
        for (int tt = 0; tt < 12; tt++) {
            int idx = tid + tt * 256;
            int wr = idx / 48, wc = idx % 48;
            Ws[wr][wc] = W[(size_t)(kt + wr) * 48 + wc];
        }
        __syncthreads();
#pragma unroll
        for (int kk = 0; kk < 64; kk++) {
            float xv = xs[r][kk];
#pragma unroll
            for (int j = 0; j < 6; j++) acc[j] += xv * Ws[kk][q + 8*j];
        }
        __syncthreads();
    }
    int grow = row0 + r;
    int b = grow / Tdim, t = grow % Tdim;
#pragma unroll
    for (int j = 0; j < 6; j++) {
        int col = q + 8*j;
        int h = col / 3, ii = col % 3;
        float v = acc[j] + bias[col];
        v = 1.f / (1.f + expf(-v));
        g_param[ii][((size_t)b*Hdim + h)*Tdim + t] = v;
    }
}

// ---------------------------------------------------------------------------
// K3: chunked Titans scan (emits fp16 hi/lo for proj GEMM)
// ---------------------------------------------------------------------------
__device__ __forceinline__ ull pk1(float v) {
    ull r; asm("mov.b64 %0, {%1, %1};" : "=l"(r) : "f"(v)); return r;
}
__device__ __forceinline__ ull fma2(ull a, ull b, ull c) {
    ull d; asm("fma.rn.f32x2 %0, %1, %2, %3;" : "=l"(d) : "l"(a), "l"(b), "l"(c)); return d;
}
__device__ __forceinline__ ull mul2(ull a, ull b) {
    ull d; asm("mul.rn.f32x2 %0, %1, %2;" : "=l"(d) : "l"(a), "l"(b)); return d;
}
__device__ __forceinline__ float2 upk(ull v) {
    float2 f; asm("mov.b64 {%0, %1}, %2;" : "=f"(f.x), "=f"(f.y) : "l"(v)); return f;
}

#define CHUNK_F (CSdim*Ddim)
#define BUF_F   (3*CHUNK_F + 48)

__global__ __launch_bounds__(512) void scan_kernel(const float* __restrict__ w,
                                                   const float* __restrict__ bln)
{
    __shared__ __align__(16) float buf[2][BUF_F];
    __shared__ float kh_s[16][64], dkh_s[16][64], o_s[16][64];
    __shared__ float w_s[64], b_s[64];

    int tid  = threadIdx.x;
    int e    = tid >> 3, g = tid & 7;
    int lane = tid & 31, wid = tid >> 5;
    int bh = blockIdx.x;
    int b  = bh >> 4, h = bh & 15;

    const float* qg = g_qkv[0] + (size_t)bh * Tdim * Ddim;
    const float* kg = g_qkv[1] + (size_t)bh * Tdim * Ddim;
    const float* vg = g_qkv[2] + (size_t)bh * Tdim * Ddim;
    const float* thg = g_param[0] + (size_t)bh * Tdim;
    const float* alg = g_param[1] + (size_t)bh * Tdim;
    const float* etg = g_param[2] + (size_t)bh * Tdim;

    if (tid < 64) { w_s[tid] = w[h*64 + tid]; b_s[tid] = bln[h*64 + tid]; }

    ull S2[4], m2[4];
#pragma unroll
    for (int i = 0; i < 4; i++) { S2[i] = 0ull; m2[i] = 0ull; }

#define PREFETCH(ci, dst)                                                     \
    do {                                                                      \
        int base4 = (ci) * (CHUNK_F/4);                                       \
        for (int idx = tid; idx < 780; idx += 512) {                          \
            if (idx < 256)                                                    \
                cpasync16(smem_u32((dst) + idx*4), (const float4*)kg + base4 + idx); \
            else if (idx < 512)                                               \
                cpasync16(smem_u32((dst) + CHUNK_F + (idx-256)*4),            \
                          (const float4*)qg + base4 + (idx-256));             \
            else if (idx < 768)                                               \
                cpasync16(smem_u32((dst) + 2*CHUNK_F + (idx-512)*4),          \
                          (const float4*)vg + base4 + (idx-512));             \
            else if (idx < 772)                                               \
                cpasync16(smem_u32((dst) + 3*CHUNK_F + (idx-768)*4),          \
                          (const float4*)(thg + (ci)*16) + (idx-768));        \
            else if (idx < 776)                                               \
                cpasync16(smem_u32((dst) + 3*CHUNK_F + 16 + (idx-772)*4),     \
                          (const float4*)(alg + (ci)*16) + (idx-772));        \
            else                                                              \
                cpasync16(smem_u32((dst) + 3*CHUNK_F + 32 + (idx-776)*4),     \
                          (const float4*)(etg + (ci)*16) + (idx-776));        \
        }                                                                     \
        cpcommit();                                                           \
    } while (0)

    PREFETCH(0, buf[0]);

    for (int ci = 0; ci < NTdim; ci++) {
        if (ci + 1 < NTdim) {
            PREFETCH(ci + 1, buf[(ci+1) & 1]);
            cpwait1();
        } else {
            cpwait0();
        }
        __syncthreads();

        float* Kp = buf[ci & 1];
        float* Qp = Kp + CHUNK_F;
        float* Vp = Kp + 2*CHUNK_F;
        float* TH = Kp + 3*CHUNK_F;
        float* AL = TH + 16;
        float* ET = TH + 32;

        {
            int c = wid;
            float k0 = Kp[c*64 + lane], k1 = Kp[c*64 + lane + 32];
            float q0 = Qp[c*64 + lane], q1 = Qp[c*64 + lane + 32];
            float sk = k0*k0 + k1*k1, sq = q0*q0 + q1*q1;
#pragma unroll
            for (int off = 16; off; off >>= 1) {
                sk += __shfl_xor_sync(0xffffffffu, sk, off);
                sq += __shfl_xor_sync(0xffffffffu, sq, off);
            }
            float rk = 1.f / fmaxf(sqrtf(sk), 1e-12f);
            float rq = 1.f / fmaxf(sqrtf(sq), 1e-12f);
            Kp[c*64 + lane] = k0*rk; Kp[c*64 + lane + 32] = k1*rk;
            Qp[c*64 + lane] = q0*rq; Qp[c*64 + lane + 32] = q1*rq;
        }
        __syncthreads();

#pragma unroll
        for (int c = 0; c < 16; c++) {
            ulonglong2 ka = *(const ulonglong2*)&Kp[c*64 + 8*g];
            ulonglong2 kb = *(const ulonglong2*)&Kp[c*64 + 8*g + 4];
            ull p2 = 0ull;
            p2 = fma2(ka.x, S2[0], p2);
            p2 = fma2(ka.y, S2[1], p2);
            p2 = fma2(kb.x, S2[2], p2);
            p2 = fma2(kb.y, S2[3], p2);
            float2 pf = upk(p2);
            float p = pf.x + pf.y;
            p += __shfl_xor_sync(0xffffffffu, p, 1);
            p += __shfl_xor_sync(0xffffffffu, p, 2);
            p += __shfl_xor_sync(0xffffffffu, p, 4);
            if (g == 0) kh_s[c][e] = p;
        }
        __syncthreads();

        {
            int c = wid;
            float x0 = kh_s[c][lane], x1 = kh_s[c][lane+32];
            float s = x0 + x1;
#pragma unroll
            for (int off = 16; off; off >>= 1) s += __shfl_xor_sync(0xffffffffu, s, off);
            float mu = s * (1.f/64.f);
            float xc0 = x0 - mu, xc1 = x1 - mu;
            float vv = xc0*xc0 + xc1*xc1;
#pragma unroll
            for (int off = 16; off; off >>= 1) vv += __shfl_xor_sync(0xffffffffu, vv, off);
            float rstd = rsqrtf(vv * (1.f/64.f) + EPSLN);
            float xh0 = xc0 * rstd, xh1 = xc1 * rstd;
            float w0 = w_s[lane], w1 = w_s[lane+32];
            float y0 = xh0*w0 + b_s[lane], y1 = xh1*w1 + b_s[lane+32];
            float dy0 = 2.f*(y0 - Vp[c*64 + lane]);
            float dy1 = 2.f*(y1 - Vp[c*64 + lane + 32]);
            float wdy0 = dy0*w0, wdy1 = dy1*w1;
            float c1 = xh0*wdy0 + xh1*wdy1;
            float c2 = wdy0 + wdy1;
#pragma unroll
            for (int off = 16; off; off >>= 1) {
                c1 += __shfl_xor_sync(0xffffffffu, c1, off);
                c2 += __shfl_xor_sync(0xffffffffu, c2, off);
            }
            c1 *= (1.f/64.f); c2 *= (1.f/64.f);
            dkh_s[c][lane]    = (wdy0 - xh0*c1 - c2) * rstd;
            dkh_s[c][lane+32] = (wdy1 - xh1*c1 - c2) * rstd;
        }
        __syncthreads();

#pragma unroll 4
        for (int c = 0; c < 16; c++) {
            float th = TH[c], al = AL[c], et = ET[c];
            float dk = dkh_s[c][e];
            ulonglong2 ka = *(const ulonglong2*)&Kp[c*64 + 8*g];
            ulonglong2 kb = *(const ulonglong2*)&Kp[c*64 + 8*g + 4];
            ulonglong2 qa = *(const ulonglong2*)&Qp[c*64 + 8*g];
            ulonglong2 qb = *(const ulonglong2*)&Qp[c*64 + 8*g + 4];
            ull kp[4] = {ka.x, ka.y, kb.x, kb.y};
            ull qp[4] = {qa.x, qa.y, qb.x, qb.y};
            ull et2  = pk1(et);
            ull oma2 = pk1(1.f - al);
            ull ntd2 = pk1(-th * dk);
            ull po2 = 0ull;
#pragma unroll
            for (int j = 0; j < 4; j++) {
                m2[j] = fma2(et2, m2[j], mul2(ntd2, kp[j]));
                S2[j] = fma2(oma2, S2[j], m2[j]);
                po2   = fma2(qp[j], S2[j], po2);
            }
            float2 pf = upk(po2);
            float po = pf.x + pf.y;
            po += __shfl_xor_sync(0xffffffffu, po, 1);
            po += __shfl_xor_sync(0xffffffffu, po, 2);
            po += __shfl_xor_sync(0xffffffffu, po, 4);
            if (g == 0) o_s[c][e] = po;
        }
        __syncthreads();

        {
            int c = wid;
            float x0 = o_s[c][lane], x1 = o_s[c][lane+32];
            float s = x0 + x1;
#pragma unroll
            for (int off = 16; off; off >>= 1) s += __shfl_xor_sync(0xffffffffu, s, off);
            float mu = s * (1.f/64.f);
            float xc0 = x0 - mu, xc1 = x1 - mu;
            float vv = xc0*xc0 + xc1*xc1;
#pragma unroll
            for (int off = 16; off; off >>= 1) vv += __shfl_xor_sync(0xffffffffu, vv, off);
            float rstd = rsqrtf(vv * (1.f/64.f) + EPSLN);
            int t = ci*16 + c;
            size_t base = ((size_t)b*Tdim + t)*Cdim + h*64;
            float v0 = xc0*rstd*w_s[lane]    + b_s[lane];
            float v1 = xc1*rstd*w_s[lane+32] + b_s[lane+32];
            __half h0 = __float2half(v0);
            __half h1 = __float2half(v1);
            g_oh[base + lane]      = h0;
            g_oh[base + lane + 32] = h1;
            g_ol[base + lane]      = __float2half(v0 - __half2float(h0));
            g_ol[base + lane + 32] = __float2half(v1 - __half2float(h1));
        }
    }
#undef PREFETCH
}

// ---------------------------------------------------------------------------
extern "C" void kernel_launch(void* const* d_in, const int* in_sizes, int n_in,
                              void* d_out, int out_size)
{
    const float* x       = (const float*)d_in[0];
    const float* W_attn  = (const float*)d_in[1];
    const float* b_attn  = (const float*)d_in[2];
    const float* W_param = (const float*)d_in[3];
    const float* b_param = (const float*)d_in[4];
    const float* W_proj  = (const float*)d_in[5];
    const float* b_proj  = (const float*)d_in[6];
    const float* w       = (const float*)d_in[7];
    const float* bb      = (const float*)d_in[8];
    float* out = (float*)d_out;

    const int SMEM_MMA = 1024 + 4*TILE_B;
    cudaFuncSetAttribute(mma_gemm<1>, cudaFuncAttributeMaxDynamicSharedMemorySize, SMEM_MMA);
    cudaFuncSetAttribute(mma_gemm<0>, cudaFuncAttributeMaxDynamicSharedMemorySize, SMEM_MMA);

    __half *xh, *xl, *wah, *wph, *oh, *ol;
    cudaGetSymbolAddress((void**)&xh,  g_xh);
    cudaGetSymbolAddress((void**)&xl,  g_xl);
    cudaGetSymbolAddress((void**)&wah, g_wah);
    cudaGetSymbolAddress((void**)&wph, g_wph);
    cudaGetSymbolAddress((void**)&oh,  g_oh);
    cudaGetSymbolAddress((void**)&ol,  g_ol);

    // launch order chosen so the ncu capture (4th launch) hits mma_gemm<1>
    transpose_w<<<dim3(96, 32), dim3(32, 8)>>>(W_attn, wah, 3*Cdim);    // 0
    convert_x<<<(BTdim*Cdim)/1024, 256>>>(x);                           // 1
    param_kernel<<<256, 256>>>(x, W_param, b_param);                    // 2
    mma_gemm<1><<<dim3(24, 64), 256, SMEM_MMA>>>(xh, xl, wah, b_attn, nullptr); // 3
    transpose_w<<<dim3(32, 32), dim3(32, 8)>>>(W_proj, wph, Cdim);      // 4
    scan_kernel<<<64, 512>>>(w, bb);                                    // 5
    mma_gemm<0><<<dim3(8, 64), 256, SMEM_MMA>>>(oh, ol, wph, b_proj, out);      // 6
}